// round 8
// baseline (speedup 1.0000x reference)
#include <cuda_runtime.h>
#include <cuda_bf16.h>
#include <math.h>

#define B_      8
#define S_      2048
#define D_      320
#define NH_     5
#define HD_     64
#define FF_     864
#define NL_     6
#define NLOOPS_ 8
#define TOK_    (B_*S_)          // 16384
#define KSEL_   1638             // int(2048*0.8)
#define QKVW_   (3*D_)           // 960
#define KPMAX_  896

typedef unsigned int       u32;
typedef unsigned long long u64;
typedef unsigned long long ull;

// ---------------- f32x2 packed helpers (attention) ---------------------------
__device__ __forceinline__ ull pk2(float x, float y) {
    ull r; asm("mov.b64 %0,{%1,%2};" : "=l"(r) : "f"(x), "f"(y)); return r;
}
__device__ __forceinline__ float2 upk(ull v) {
    float2 f; asm("mov.b64 {%0,%1},%2;" : "=f"(f.x), "=f"(f.y) : "l"(v)); return f;
}
__device__ __forceinline__ ull fma2(ull a, ull b, ull c) {
    ull d; asm("fma.rn.f32x2 %0,%1,%2,%3;" : "=l"(d) : "l"(a), "l"(b), "l"(c)); return d;
}
__device__ __forceinline__ ull mul2(ull a, ull b) {
    ull d; asm("mul.rn.f32x2 %0,%1,%2;" : "=l"(d) : "l"(a), "l"(b)); return d;
}
__device__ __forceinline__ ull add2(ull a, ull b) {
    ull d; asm("add.rn.f32x2 %0,%1,%2;" : "=l"(d) : "l"(a), "l"(b)); return d;
}

// ---------------- mma.sync helpers -------------------------------------------
__device__ __forceinline__ u32 s2u(const void* p) {
    u32 a;
    asm("{ .reg .u64 t; cvta.to.shared.u64 t, %1; cvt.u32.u64 %0, t; }" : "=r"(a) : "l"(p));
    return a;
}
__device__ __forceinline__ void ldsm4(u32& r0, u32& r1, u32& r2, u32& r3, u32 addr) {
    asm volatile("ldmatrix.sync.aligned.m8n8.x4.shared.b16 {%0,%1,%2,%3},[%4];"
                 : "=r"(r0), "=r"(r1), "=r"(r2), "=r"(r3) : "r"(addr));
}
__device__ __forceinline__ void mma16816(float* c, const u32* a, u32 b0, u32 b1) {
    asm volatile(
        "mma.sync.aligned.m16n8k16.row.col.f32.bf16.bf16.f32 "
        "{%0,%1,%2,%3},{%4,%5,%6,%7},{%8,%9},{%0,%1,%2,%3};"
        : "+f"(c[0]), "+f"(c[1]), "+f"(c[2]), "+f"(c[3])
        : "r"(a[0]), "r"(a[1]), "r"(a[2]), "r"(a[3]), "r"(b0), "r"(b1));
}

// ---------------- scratch (device globals; no allocations allowed) ----------
static __device__ float g_X[TOK_*D_];                    // residual stream
static __device__ float g_H[TOK_*D_];                    // rmsnorm output
static __device__ float g_QKV[TOK_*QKVW_];               // qkv projections
static __device__ float g_AO[TOK_*D_];                   // attention output
static __device__ float g_G[TOK_*FF_];                   // mlp intermediate
static __device__ float g_T1[TOK_*FF_];                  // gate pre-activation
static __device__ float g_RS[TOK_];                      // mask*prob per token
static __device__ float g_P[TOK_];                       // router probs
static __device__ __nv_bfloat16 g_Ahi[(size_t)TOK_*KPMAX_];
static __device__ __nv_bfloat16 g_Alo[(size_t)TOK_*KPMAX_];
static __device__ __nv_bfloat16 g_Whi[QKVW_*KPMAX_];
static __device__ __nv_bfloat16 g_Wlo[QKVW_*KPMAX_];

// ---------------- embedding + iter_emb --------------------------------------
__global__ void embed_kernel(const int* __restrict__ ids, const int* __restrict__ iter,
                             const float* __restrict__ emb, const float* __restrict__ iemb)
{
    int t = blockIdx.x;
    int id = ids[t];
    int it = iter[0];
    const float* e = emb + (size_t)id * D_;
    const float* a = (it >= 0 && it < NLOOPS_) ? (iemb + (size_t)it * D_) : nullptr;
    for (int d = threadIdx.x; d < D_; d += blockDim.x) {
        float v = e[d];
        if (a) v += a[d];
        g_X[(size_t)t * D_ + d] = v;
    }
}

// ---------------- rmsnorm: src is always g_X; dst = g_H or out ---------------
__global__ __launch_bounds__(128) void rmsnorm_kernel(const float* __restrict__ w,
                                                      float* __restrict__ outp)
{
    int t = blockIdx.x;
    const float* x = g_X + (size_t)t * D_;
    float* dst = outp ? (outp + (size_t)t * D_) : (g_H + (size_t)t * D_);
    float s = 0.f;
    for (int d = threadIdx.x; d < D_; d += 128) { float v = x[d]; s = fmaf(v, v, s); }
    #pragma unroll
    for (int o = 16; o > 0; o >>= 1) s += __shfl_xor_sync(0xffffffffu, s, o);
    __shared__ float red[4];
    if ((threadIdx.x & 31) == 0) red[threadIdx.x >> 5] = s;
    __syncthreads();
    s = red[0] + red[1] + red[2] + red[3];
    float inv = rsqrtf(s * (1.f / D_) + 1e-6f);
    for (int d = threadIdx.x; d < D_; d += 128) dst[d] = w[d] * x[d] * inv;
}

// ---------------- fp32 -> bf16 hi/lo conversions -----------------------------
__global__ __launch_bounds__(128) void conv_a_kernel(int asel, int K, int Kp)
{
    const float* src = (asel == 0) ? g_H : (asel == 1) ? g_AO : g_G;
    int t = blockIdx.x;
    const float* s = src + (size_t)t * K;
    __nv_bfloat16* hi = g_Ahi + (size_t)t * Kp;
    __nv_bfloat16* lo = g_Alo + (size_t)t * Kp;
    for (int d = threadIdx.x * 2; d < Kp; d += 256) {
        float v0 = (d < K) ? s[d] : 0.f;
        float v1 = (d + 1 < K) ? s[d + 1] : 0.f;
        __nv_bfloat16 h0 = __float2bfloat16(v0);
        __nv_bfloat16 h1 = __float2bfloat16(v1);
        __nv_bfloat16 l0 = __float2bfloat16(v0 - __bfloat162float(h0));
        __nv_bfloat16 l1 = __float2bfloat16(v1 - __bfloat162float(h1));
        hi[d] = h0; hi[d + 1] = h1;
        lo[d] = l0; lo[d + 1] = l1;
    }
}
__global__ __launch_bounds__(128) void conv_w_kernel(const float* __restrict__ W,
                                                     int K, int Kp)
{
    int n = blockIdx.x;
    const float* s = W + (size_t)n * K;
    __nv_bfloat16* hi = g_Whi + (size_t)n * Kp;
    __nv_bfloat16* lo = g_Wlo + (size_t)n * Kp;
    for (int d = threadIdx.x * 2; d < Kp; d += 256) {
        float v0 = (d < K) ? s[d] : 0.f;
        float v1 = (d + 1 < K) ? s[d + 1] : 0.f;
        __nv_bfloat16 h0 = __float2bfloat16(v0);
        __nv_bfloat16 h1 = __float2bfloat16(v1);
        __nv_bfloat16 l0 = __float2bfloat16(v0 - __bfloat162float(h0));
        __nv_bfloat16 l1 = __float2bfloat16(v1 - __bfloat162float(h1));
        hi[d] = h0; hi[d + 1] = h1;
        lo[d] = l0; lo[d + 1] = l1;
    }
}

// ====== HMMA bf16-split GEMM: C[M,N] (op)= A[M,K] @ W[N,K]^T ================
// 128x64 CTA tile, 8 warps (32x32 each), BK=32, smem stride 40 halves.
// acc = Ahi*Bhi + Ahi*Blo + Alo*Bhi  (fp32 accumulate in registers)
// mode: 0 C=acc | 1 C+=acc | 2 C+=g_RS[m]*acc | 3 C=silu(g_T1)*acc
// csel: 0=g_QKV 1=g_X 2=g_T1 3=g_G
#define AST_ 40
__global__ __launch_bounds__(256) void mma_gemm_kernel(int N, int Kp, int nch,
                                                       int mode, int csel)
{
    __shared__ __nv_bfloat16 Ah[128 * AST_], Al[128 * AST_];
    __shared__ __nv_bfloat16 Bh[64 * AST_],  Bl[64 * AST_];
    int tid = threadIdx.x, lane = tid & 31, wid = tid >> 5;
    int n0 = blockIdx.x * 64, m0 = blockIdx.y * 128;
    int mbase = (wid >> 1) * 32;      // warp row offset within tile
    int nbase = (wid & 1) * 32;       // warp col offset within tile

    // precomputed ldmatrix lane addresses (constant across chunks)
    u32 aAh = s2u(Ah), aAl = s2u(Al), aBh = s2u(Bh), aBl = s2u(Bl);
    u32 adA[2][2][2];  // [hi/lo][mt][ks]
    u32 adB[2][2][2];  // [hi/lo][pair][ks]
    #pragma unroll
    for (int mt = 0; mt < 2; mt++)
        #pragma unroll
        for (int ks = 0; ks < 2; ks++) {
            u32 off = (u32)((mbase + mt * 16 + (lane & 15)) * AST_ +
                            ks * 16 + (lane >> 4) * 8) * 2;
            adA[0][mt][ks] = aAh + off;
            adA[1][mt][ks] = aAl + off;
        }
    #pragma unroll
    for (int pr = 0; pr < 2; pr++)
        #pragma unroll
        for (int ks = 0; ks < 2; ks++) {
            int sel = lane >> 3;                       // 0..3
            int nr = nbase + pr * 16 + (sel >> 1) * 8 + (lane & 7);
            int kc = ks * 16 + (sel & 1) * 8;
            u32 off = (u32)(nr * AST_ + kc) * 2;
            adB[0][pr][ks] = aBh + off;
            adB[1][pr][ks] = aBl + off;
        }

    float acc[2][4][4];
    #pragma unroll
    for (int mt = 0; mt < 2; mt++)
        #pragma unroll
        for (int nt = 0; nt < 4; nt++)
            #pragma unroll
            for (int q = 0; q < 4; q++) acc[mt][nt][q] = 0.f;

    for (int ch = 0; ch < nch; ch++) {
        int k0 = ch * 32;
        __syncthreads();
        // stage A hi/lo: 128 rows x 32 halves
        #pragma unroll
        for (int it = 0; it < 2; it++) {
            int idx = it * 256 + tid;            // 0..511
            int row = idx >> 2, sec = idx & 3;
            size_t eo = (size_t)(m0 + row) * Kp + k0 + sec * 8;
            u32 so = (u32)(row * AST_ + sec * 8) * 2;
            *(uint4*)((char*)Ah + so) = *(const uint4*)(g_Ahi + eo);
            *(uint4*)((char*)Al + so) = *(const uint4*)(g_Alo + eo);
        }
        // stage B hi/lo: 64 rows x 32 halves (zero-pad rows >= N)
        {
            int row = tid >> 2, sec = tid & 3;
            bool ok = (n0 + row) < N;
            size_t eo = (size_t)(ok ? (n0 + row) : 0) * Kp + k0 + sec * 8;
            u32 so = (u32)(row * AST_ + sec * 8) * 2;
            uint4 v = make_uint4(0, 0, 0, 0), w = make_uint4(0, 0, 0, 0);
            if (ok) { v = *(const uint4*)(g_Whi + eo); w = *(const uint4*)(g_Wlo + eo); }
            *(uint4*)((char*)Bh + so) = v;
            *(uint4*)((char*)Bl + so) = w;
        }
        __syncthreads();
        #pragma unroll
        for (int ks = 0; ks < 2; ks++) {
            u32 ah[2][4], al[2][4], bh[2][4], bl[2][4];
            #pragma unroll
            for (int mt = 0; mt < 2; mt++) {
                ldsm4(ah[mt][0], ah[mt][1], ah[mt][2], ah[mt][3], adA[0][mt][ks]);
                ldsm4(al[mt][0], al[mt][1], al[mt][2], al[mt][3], adA[1][mt][ks]);
            }
            #pragma unroll
            for (int pr = 0; pr < 2; pr++) {
                ldsm4(bh[pr][0], bh[pr][1], bh[pr][2], bh[pr][3], adB[0][pr][ks]);
                ldsm4(bl[pr][0], bl[pr][1], bl[pr][2], bl[pr][3], adB[1][pr][ks]);
            }
            #pragma unroll
            for (int mt = 0; mt < 2; mt++)
                #pragma unroll
                for (int nt = 0; nt < 4; nt++) {
                    int pr = nt >> 1, of = (nt & 1) * 2;
                    mma16816(acc[mt][nt], ah[mt], bh[pr][of], bh[pr][of + 1]);
                    mma16816(acc[mt][nt], ah[mt], bl[pr][of], bl[pr][of + 1]);
                    mma16816(acc[mt][nt], al[mt], bh[pr][of], bh[pr][of + 1]);
                }
        }
    }

    // epilogue
    int grp = lane >> 2, tg = lane & 3;
    float* C = (csel == 0) ? g_QKV : (csel == 1) ? g_X : (csel == 2) ? g_T1 : g_G;
    #pragma unroll
    for (int mt = 0; mt < 2; mt++) {
        int r0 = m0 + mbase + mt * 16 + grp;
        int r1 = r0 + 8;
        float rs0 = 1.f, rs1 = 1.f;
        if (mode == 2) { rs0 = g_RS[r0]; rs1 = g_RS[r1]; }
        #pragma unroll
        for (int nt = 0; nt < 4; nt++) {
            int nc = n0 + nbase + nt * 8 + tg * 2;
            if (nc >= N) continue;
            float* p0 = C + (size_t)r0 * N + nc;
            float* p1 = C + (size_t)r1 * N + nc;
            float a0 = acc[mt][nt][0], a1 = acc[mt][nt][1];
            float a2 = acc[mt][nt][2], a3 = acc[mt][nt][3];
            if (mode == 0) {
                *(float2*)p0 = make_float2(a0, a1);
                *(float2*)p1 = make_float2(a2, a3);
            } else if (mode == 1) {
                float2 o0 = *(const float2*)p0, o1 = *(const float2*)p1;
                *(float2*)p0 = make_float2(o0.x + a0, o0.y + a1);
                *(float2*)p1 = make_float2(o1.x + a2, o1.y + a3);
            } else if (mode == 2) {
                float2 o0 = *(const float2*)p0, o1 = *(const float2*)p1;
                *(float2*)p0 = make_float2(o0.x + rs0 * a0, o0.y + rs0 * a1);
                *(float2*)p1 = make_float2(o1.x + rs1 * a2, o1.y + rs1 * a3);
            } else {
                const float* t0 = g_T1 + (size_t)r0 * N + nc;
                const float* t1 = g_T1 + (size_t)r1 * N + nc;
                float2 g0 = *(const float2*)t0, g1 = *(const float2*)t1;
                *(float2*)p0 = make_float2(
                    (g0.x / (1.f + __expf(-g0.x))) * a0,
                    (g0.y / (1.f + __expf(-g0.y))) * a1);
                *(float2*)p1 = make_float2(
                    (g1.x / (1.f + __expf(-g1.x))) * a2,
                    (g1.y / (1.f + __expf(-g1.y))) * a3);
            }
        }
    }
}

// ---------------- RoPE in-place on q,k parts of g_QKV ------------------------
__global__ __launch_bounds__(160) void rope_kernel()
{
    int t = blockIdx.x;
    int s = t & (S_ - 1);
    int h = threadIdx.x >> 5;       // 0..4
    int i = threadIdx.x & 31;       // pair index 0..31
    float freq = expf(-((float)(2 * i) / (float)HD_) * 9.210340371976184f); // ln(10000)
    float ang = (float)s * freq;
    float sn, cs;
    sincosf(ang, &sn, &cs);
    float* qb = g_QKV + (size_t)t * QKVW_ + h * HD_;
    float q1 = qb[i], q2 = qb[i + 32];
    qb[i]      = q1 * cs - q2 * sn;
    qb[i + 32] = q2 * cs + q1 * sn;
    float* kb = qb + D_;
    float k1 = kb[i], k2 = kb[i + 32];
    kb[i]      = k1 * cs - k2 * sn;
    kb[i + 32] = k2 * cs + k1 * sn;
}

// ---------------- causal flash attention, f32x2 + 4-way QK ILP ---------------
__global__ __launch_bounds__(128) void attn_kernel()
{
    int qb = blockIdx.x, h = blockIdx.y, b = blockIdx.z;
    int tid = threadIdx.x;
    int sq = qb * 128 + tid;
    const float4* qp = (const float4*)(g_QKV + (size_t)(b * S_ + sq) * QKVW_ + h * HD_);
    ull q2r[32], o2[32];
    #pragma unroll
    for (int i = 0; i < 16; i++) {
        float4 v = qp[i];
        q2r[2*i+0] = pk2(v.x * 0.125f, v.y * 0.125f);
        q2r[2*i+1] = pk2(v.z * 0.125f, v.w * 0.125f);
    }
    #pragma unroll
    for (int i = 0; i < 32; i++) o2[i] = 0ULL;
    float m = -1e30f, l = 0.f;
    __shared__ __align__(16) float Ks[64 * 64];
    __shared__ __align__(16) float Vs[64 * 64];
    int kend = qb * 128 + 128;
    for (int j0 = 0; j0 < kend; j0 += 64) {
        __syncthreads();
        #pragma unroll
        for (int it = 0; it < 8; it++) {
            int idx = it * 128 + tid;           // float4 index in 64x16
            int r = idx >> 4, c4 = idx & 15;
            const float4* kv = (const float4*)(g_QKV + (size_t)(b * S_ + j0 + r) * QKVW_ + h * HD_);
            ((float4*)Ks)[idx] = kv[80 + c4];   // +320 floats (K)
            ((float4*)Vs)[idx] = kv[160 + c4];  // +640 floats (V)
        }
        __syncthreads();
        if (j0 > sq) continue;
        int jm = sq - j0;
        int jend = (jm >= 63) ? 64 : (jm + 1);
        for (int j = 0; j < jend; j++) {
            const ulonglong2* kr = (const ulonglong2*)(Ks + j * 64);
            ull sa = 0ULL, sb2 = 0ULL, sc = 0ULL, sd = 0ULL;
            #pragma unroll
            for (int i = 0; i < 8; i++) {
                ulonglong2 k0 = kr[2*i], k1 = kr[2*i+1];
                sa  = fma2(q2r[4*i+0], k0.x, sa);
                sb2 = fma2(q2r[4*i+1], k0.y, sb2);
                sc  = fma2(q2r[4*i+2], k1.x, sc);
                sd  = fma2(q2r[4*i+3], k1.y, sd);
            }
            float2 sf = upk(add2(add2(sa, sb2), add2(sc, sd)));
            float s = sf.x + sf.y;
            if (s > m) {
                float c = __expf(m - s);
                m = s; l *= c;
                ull c2 = pk2(c, c);
                #pragma unroll
                for (int i = 0; i < 32; i++) o2[i] = mul2(o2[i], c2);
            }
            float p = __expf(s - m);
            l += p;
            ull p2 = pk2(p, p);
            const ulonglong2* vr = (const ulonglong2*)(Vs + j * 64);
            #pragma unroll
            for (int i = 0; i < 16; i++) {
                ulonglong2 vv = vr[i];
                o2[2*i+0] = fma2(p2, vv.x, o2[2*i+0]);
                o2[2*i+1] = fma2(p2, vv.y, o2[2*i+1]);
            }
        }
    }
    float invl = 1.f / l;
    float4* op = (float4*)(g_AO + (size_t)(b * S_ + sq) * D_ + h * HD_);
    #pragma unroll
    for (int i = 0; i < 16; i++) {
        float2 a = upk(o2[2*i]), c = upk(o2[2*i+1]);
        op[i] = make_float4(a.x * invl, a.y * invl, c.x * invl, c.y * invl);
    }
}

// ---------------- router: sigmoid(X . router_w) one warp per token -----------
__global__ __launch_bounds__(128) void router_kernel(const float* __restrict__ rw)
{
    int t = blockIdx.x * 4 + (threadIdx.x >> 5);
    int lane = threadIdx.x & 31;
    const float* x = g_X + (size_t)t * D_;
    float s = 0.f;
    for (int d = lane; d < D_; d += 32) s = fmaf(x[d], rw[d], s);
    #pragma unroll
    for (int o = 16; o > 0; o >>= 1) s += __shfl_xor_sync(0xffffffffu, s, o);
    if (lane == 0) g_P[t] = 1.f / (1.f + expf(-s));
}

// ---------------- exact stable top-k selection -> g_RS = mask * prob ---------
__global__ __launch_bounds__(256) void select_kernel()
{
    __shared__ float p[S_];
    int b = blockIdx.x;
    for (int t = threadIdx.x; t < S_; t += 256) p[t] = g_P[b * S_ + t];
    __syncthreads();
    int t = blockIdx.y * 256 + threadIdx.x;
    float pt = p[t];
    int rank = 0;
    for (int j = 0; j < S_; j++) {
        float pj = p[j];
        rank += (pj > pt) ? 1 : ((pj == pt && j < t) ? 1 : 0);
    }
    g_RS[b * S_ + t] = (rank < KSEL_) ? pt : 0.f;
}

// ---------------- driver ------------------------------------------------------
extern "C" void kernel_launch(void* const* d_in, const int* in_sizes, int n_in,
                              void* d_out, int out_size)
{
    const int*   ids          = (const int*)d_in[0];
    const int*   iter         = (const int*)d_in[1];
    const float* emb          = (const float*)d_in[2];
    const float* iemb         = (const float*)d_in[3];
    const float* attn_norm_w  = (const float*)d_in[4];
    const float* Wqkv         = (const float*)d_in[5];
    const float* wo_w         = (const float*)d_in[6];
    const float* router_w     = (const float*)d_in[7];
    const float* mlp_norm_w   = (const float*)d_in[8];
    const float* gate_w       = (const float*)d_in[9];
    const float* up_w         = (const float*)d_in[10];
    const float* down_w       = (const float*)d_in[11];
    const float* final_norm_w = (const float*)d_in[12];
    float* out = (float*)d_out;

    embed_kernel<<<TOK_, 128>>>(ids, iter, emb, iemb);
    for (int l = 0; l < NL_; l++) {
        // ---- attention block ----
        rmsnorm_kernel<<<TOK_, 128>>>(attn_norm_w + l * D_, nullptr);
        conv_a_kernel<<<TOK_, 128>>>(0, D_, D_);
        conv_w_kernel<<<QKVW_, 128>>>(Wqkv + (size_t)l * QKVW_ * D_, D_, D_);
        mma_gemm_kernel<<<dim3(15, 128), 256>>>(QKVW_, D_, 10, 0, 0);
        rope_kernel<<<TOK_, 160>>>();
        attn_kernel<<<dim3(S_ / 128, NH_, B_), 128>>>();
        conv_a_kernel<<<TOK_, 128>>>(1, D_, D_);
        conv_w_kernel<<<D_, 128>>>(wo_w + (size_t)l * D_ * D_, D_, D_);
        mma_gemm_kernel<<<dim3(5, 128), 256>>>(D_, D_, 10, 1, 1);
        // ---- router / moe ----
        router_kernel<<<TOK_ / 4, 128>>>(router_w + l * D_);
        select_kernel<<<dim3(B_, 8), 256>>>();
        rmsnorm_kernel<<<TOK_, 128>>>(mlp_norm_w + l * D_, nullptr);
        conv_a_kernel<<<TOK_, 128>>>(0, D_, D_);
        conv_w_kernel<<<FF_, 128>>>(gate_w + (size_t)l * FF_ * D_, D_, D_);
        mma_gemm_kernel<<<dim3(14, 128), 256>>>(FF_, D_, 10, 0, 2);   // T1 = H@gate^T
        conv_w_kernel<<<FF_, 128>>>(up_w + (size_t)l * FF_ * D_, D_, D_);
        mma_gemm_kernel<<<dim3(14, 128), 256>>>(FF_, D_, 10, 3, 3);   // G = silu(T1)*up
        conv_a_kernel<<<TOK_, 128>>>(2, FF_, FF_);
        conv_w_kernel<<<D_, 128>>>(down_w + (size_t)l * D_ * FF_, FF_, FF_);
        mma_gemm_kernel<<<dim3(5, 128), 256>>>(D_, FF_, 27, 2, 1);    // X += rs*down
    }
    rmsnorm_kernel<<<TOK_, 128>>>(final_norm_w, out);
}

// round 10
// speedup vs baseline: 1.5448x; 1.5448x over previous
#include <cuda_runtime.h>
#include <cuda_bf16.h>
#include <math.h>

#define B_      8
#define S_      2048
#define D_      320
#define NH_     5
#define HD_     64
#define FF_     864
#define NL_     6
#define NLOOPS_ 8
#define TOK_    (B_*S_)          // 16384
#define KSEL_   1638             // int(2048*0.8)
#define QKVW_   (3*D_)           // 960
#define KPMAX_  896

typedef unsigned int       u32;
typedef unsigned long long u64;
typedef unsigned long long ull;

// ---------------- f32x2 packed helpers (attention) ---------------------------
__device__ __forceinline__ ull pk2(float x, float y) {
    ull r; asm("mov.b64 %0,{%1,%2};" : "=l"(r) : "f"(x), "f"(y)); return r;
}
__device__ __forceinline__ float2 upk(ull v) {
    float2 f; asm("mov.b64 {%0,%1},%2;" : "=f"(f.x), "=f"(f.y) : "l"(v)); return f;
}
__device__ __forceinline__ ull fma2(ull a, ull b, ull c) {
    ull d; asm("fma.rn.f32x2 %0,%1,%2,%3;" : "=l"(d) : "l"(a), "l"(b), "l"(c)); return d;
}
__device__ __forceinline__ ull mul2(ull a, ull b) {
    ull d; asm("mul.rn.f32x2 %0,%1,%2;" : "=l"(d) : "l"(a), "l"(b)); return d;
}
__device__ __forceinline__ ull add2(ull a, ull b) {
    ull d; asm("add.rn.f32x2 %0,%1,%2;" : "=l"(d) : "l"(a), "l"(b)); return d;
}

// ---------------- mma.sync / cp.async helpers --------------------------------
__device__ __forceinline__ u32 s2u(const void* p) {
    u32 a;
    asm("{ .reg .u64 t; cvta.to.shared.u64 t, %1; cvt.u32.u64 %0, t; }" : "=r"(a) : "l"(p));
    return a;
}
__device__ __forceinline__ void ldsm4(u32& r0, u32& r1, u32& r2, u32& r3, u32 addr) {
    asm volatile("ldmatrix.sync.aligned.m8n8.x4.shared.b16 {%0,%1,%2,%3},[%4];"
                 : "=r"(r0), "=r"(r1), "=r"(r2), "=r"(r3) : "r"(addr));
}
__device__ __forceinline__ void mma16816(float* c, const u32* a, u32 b0, u32 b1) {
    asm volatile(
        "mma.sync.aligned.m16n8k16.row.col.f32.bf16.bf16.f32 "
        "{%0,%1,%2,%3},{%4,%5,%6,%7},{%8,%9},{%0,%1,%2,%3};"
        : "+f"(c[0]), "+f"(c[1]), "+f"(c[2]), "+f"(c[3])
        : "r"(a[0]), "r"(a[1]), "r"(a[2]), "r"(a[3]), "r"(b0), "r"(b1));
}
__device__ __forceinline__ void cpa16(u32 s, const void* g, u32 src_bytes) {
    asm volatile("cp.async.cg.shared.global [%0],[%1],16,%2;"
                 :: "r"(s), "l"(g), "r"(src_bytes));
}
__device__ __forceinline__ void cpa_commit() {
    asm volatile("cp.async.commit_group;");
}
__device__ __forceinline__ void cpa_wait0() {
    asm volatile("cp.async.wait_group 0;");
}

// ---------------- scratch (device globals; no allocations allowed) ----------
static __device__ float g_X[TOK_*D_];                    // residual stream
static __device__ float g_QKV[TOK_*QKVW_];               // qkv projections
static __device__ float g_T1[TOK_*FF_];                  // gate pre-activation
static __device__ float g_RS[TOK_];                      // mask*prob per token
static __device__ float g_P[TOK_];                       // router probs
static __device__ __nv_bfloat16 g_Ahi[(size_t)TOK_*D_];  // activation hi (stride D_)
static __device__ __nv_bfloat16 g_Alo[(size_t)TOK_*D_];
static __device__ __nv_bfloat16 g_Ghi[(size_t)TOK_*FF_]; // mlp intermediate hi
static __device__ __nv_bfloat16 g_Glo[(size_t)TOK_*FF_];
static __device__ __nv_bfloat16 g_Whi[QKVW_*KPMAX_];
static __device__ __nv_bfloat16 g_Wlo[QKVW_*KPMAX_];

__device__ __forceinline__ void split_store(__nv_bfloat16* hi, __nv_bfloat16* lo,
                                            float v) {
    __nv_bfloat16 h = __float2bfloat16(v);
    *hi = h;
    *lo = __float2bfloat16(v - __bfloat162float(h));
}

// ---------------- embedding + iter_emb --------------------------------------
__global__ void embed_kernel(const int* __restrict__ ids, const int* __restrict__ iter,
                             const float* __restrict__ emb, const float* __restrict__ iemb)
{
    int t = blockIdx.x;
    int id = ids[t];
    int it = iter[0];
    const float* e = emb + (size_t)id * D_;
    const float* a = (it >= 0 && it < NLOOPS_) ? (iemb + (size_t)it * D_) : nullptr;
    for (int d = threadIdx.x; d < D_; d += blockDim.x) {
        float v = e[d];
        if (a) v += a[d];
        g_X[(size_t)t * D_ + d] = v;
    }
}

// ------ rmsnorm fused with bf16 hi/lo split -> g_Ahi/g_Alo -------------------
__global__ __launch_bounds__(128) void rmsnorm_kernel(const float* __restrict__ w,
                                                      float* __restrict__ outp)
{
    int t = blockIdx.x;
    const float* x = g_X + (size_t)t * D_;
    float s = 0.f;
    for (int d = threadIdx.x; d < D_; d += 128) { float v = x[d]; s = fmaf(v, v, s); }
    #pragma unroll
    for (int o = 16; o > 0; o >>= 1) s += __shfl_xor_sync(0xffffffffu, s, o);
    __shared__ float red[4];
    if ((threadIdx.x & 31) == 0) red[threadIdx.x >> 5] = s;
    __syncthreads();
    s = red[0] + red[1] + red[2] + red[3];
    float inv = rsqrtf(s * (1.f / D_) + 1e-6f);
    if (outp) {
        float* dst = outp + (size_t)t * D_;
        for (int d = threadIdx.x; d < D_; d += 128) dst[d] = w[d] * x[d] * inv;
    } else {
        __nv_bfloat16* hi = g_Ahi + (size_t)t * D_;
        __nv_bfloat16* lo = g_Alo + (size_t)t * D_;
        for (int d = threadIdx.x; d < D_; d += 128)
            split_store(hi + d, lo + d, w[d] * x[d] * inv);
    }
}

// ---------------- weight fp32 -> bf16 hi/lo ----------------------------------
__global__ __launch_bounds__(128) void conv_w_kernel(const float* __restrict__ W, int K)
{
    int n = blockIdx.x;
    const float* s = W + (size_t)n * K;
    __nv_bfloat16* hi = g_Whi + (size_t)n * K;
    __nv_bfloat16* lo = g_Wlo + (size_t)n * K;
    for (int d = threadIdx.x; d < K; d += 128)
        split_store(hi + d, lo + d, s[d]);
}

// ====== HMMA bf16-split GEMM, cp.async 2-stage pipeline =====================
// C[M,N] (op)= A[M,K] @ W[N,K]^T ; 128x64 CTA tile, 8 warps, BK=32.
// acc = Ahi*Bhi + Ahi*Blo + Alo*Bhi
// asel: 0 -> A = g_Ahi/g_Alo ; 1 -> A = g_Ghi/g_Glo
// mode: 0 C=acc | 1 C+=acc | 2 C+=g_RS[m]*acc | 3 bf16split(silu(g_T1)*acc)->g_Ghi/lo
// csel: 0=g_QKV 1=g_X 2=g_T1 (mode 3 ignores csel)
#define AST_    40
#define AH_SZ   (128*AST_*2)     // 10240 bytes
#define BH_SZ   (64*AST_*2)      // 5120 bytes
#define BUF_SZ  (2*AH_SZ + 2*BH_SZ)   // 30720
#define SMEM_MM (2*BUF_SZ)            // 61440

__global__ __launch_bounds__(256, 2) void mma_gemm_kernel(int N, int Kp, int nch,
                                                          int mode, int csel, int asel)
{
    extern __shared__ char dsm[];
    u32 sb = s2u(dsm);
    int tid = threadIdx.x, lane = tid & 31, wid = tid >> 5;
    int n0 = blockIdx.x * 64, m0 = blockIdx.y * 128;
    int mbase = (wid >> 1) * 32;
    int nbase = (wid & 1) * 32;

    const __nv_bfloat16* Ahi = asel ? g_Ghi : g_Ahi;
    const __nv_bfloat16* Alo = asel ? g_Glo : g_Alo;

    // staging thread mapping
    int arow0 = tid >> 2, asec = tid & 3;
    int brow = tid >> 2, bsec = tid & 3;
    u32 a_sof = (u32)(arow0 * AST_ + asec * 8) * 2;
    u32 b_sof = (u32)(brow * AST_ + bsec * 8) * 2;
    bool bok = (n0 + brow) < N;
    size_t a_go0 = (size_t)(m0 + arow0) * Kp + asec * 8;
    size_t a_go1 = (size_t)(m0 + arow0 + 64) * Kp + asec * 8;
    size_t b_go  = (size_t)(bok ? (n0 + brow) : 0) * Kp + bsec * 8;
    u32 bbytes = bok ? 16u : 0u;

    // ldmatrix lane offsets
    u32 adA[2][2], adB[2][2];
    #pragma unroll
    for (int mt = 0; mt < 2; mt++)
        #pragma unroll
        for (int ks = 0; ks < 2; ks++)
            adA[mt][ks] = (u32)((mbase + mt * 16 + (lane & 15)) * AST_ +
                                ks * 16 + (lane >> 4) * 8) * 2;
    #pragma unroll
    for (int pr = 0; pr < 2; pr++)
        #pragma unroll
        for (int ks = 0; ks < 2; ks++) {
            int sel = lane >> 3;
            int nr = nbase + pr * 16 + (sel >> 1) * 8 + (lane & 7);
            int kc = ks * 16 + (sel & 1) * 8;
            adB[pr][ks] = (u32)(nr * AST_ + kc) * 2;
        }

    float acc[2][4][4];
    #pragma unroll
    for (int mt = 0; mt < 2; mt++)
        #pragma unroll
        for (int nt = 0; nt < 4; nt++)
            #pragma unroll
            for (int q = 0; q < 4; q++) acc[mt][nt][q] = 0.f;

    // prologue: issue chunk 0 into buffer 0
    {
        u32 bb = sb;
        cpa16(bb + a_sof, Ahi + a_go0, 16);
        cpa16(bb + a_sof + (u32)(64 * AST_ * 2), Ahi + a_go1, 16);
        cpa16(bb + AH_SZ + a_sof, Alo + a_go0, 16);
        cpa16(bb + AH_SZ + a_sof + (u32)(64 * AST_ * 2), Alo + a_go1, 16);
        cpa16(bb + 2 * AH_SZ + b_sof, g_Whi + b_go, bbytes);
        cpa16(bb + 2 * AH_SZ + BH_SZ + b_sof, g_Wlo + b_go, bbytes);
        cpa_commit();
    }

    for (int c = 0; c < nch; c++) {
        cpa_wait0();
        __syncthreads();
        if (c + 1 < nch) {
            int ko = (c + 1) * 32;
            u32 bb = sb + ((c + 1) & 1) * BUF_SZ;
            cpa16(bb + a_sof, Ahi + a_go0 + ko, 16);
            cpa16(bb + a_sof + (u32)(64 * AST_ * 2), Ahi + a_go1 + ko, 16);
            cpa16(bb + AH_SZ + a_sof, Alo + a_go0 + ko, 16);
            cpa16(bb + AH_SZ + a_sof + (u32)(64 * AST_ * 2), Alo + a_go1 + ko, 16);
            cpa16(bb + 2 * AH_SZ + b_sof, g_Whi + b_go + ko, bbytes);
            cpa16(bb + 2 * AH_SZ + BH_SZ + b_sof, g_Wlo + b_go + ko, bbytes);
            cpa_commit();
        }
        u32 bb = sb + (c & 1) * BUF_SZ;
        u32 baA = bb, baAl = bb + AH_SZ;
        u32 baB = bb + 2 * AH_SZ, baBl = bb + 2 * AH_SZ + BH_SZ;
        #pragma unroll
        for (int ks = 0; ks < 2; ks++) {
            u32 ah[2][4], al[2][4], bh[2][4], bl[2][4];
            #pragma unroll
            for (int mt = 0; mt < 2; mt++) {
                ldsm4(ah[mt][0], ah[mt][1], ah[mt][2], ah[mt][3], baA + adA[mt][ks]);
                ldsm4(al[mt][0], al[mt][1], al[mt][2], al[mt][3], baAl + adA[mt][ks]);
            }
            #pragma unroll
            for (int pr = 0; pr < 2; pr++) {
                ldsm4(bh[pr][0], bh[pr][1], bh[pr][2], bh[pr][3], baB + adB[pr][ks]);
                ldsm4(bl[pr][0], bl[pr][1], bl[pr][2], bl[pr][3], baBl + adB[pr][ks]);
            }
            #pragma unroll
            for (int mt = 0; mt < 2; mt++)
                #pragma unroll
                for (int nt = 0; nt < 4; nt++) {
                    int pr = nt >> 1, of = (nt & 1) * 2;
                    mma16816(acc[mt][nt], ah[mt], bh[pr][of], bh[pr][of + 1]);
                    mma16816(acc[mt][nt], ah[mt], bl[pr][of], bl[pr][of + 1]);
                    mma16816(acc[mt][nt], al[mt], bh[pr][of], bh[pr][of + 1]);
                }
        }
    }

    // epilogue
    int grp = lane >> 2, tg = lane & 3;
    float* C = (csel == 0) ? g_QKV : (csel == 1) ? g_X : g_T1;
    #pragma unroll
    for (int mt = 0; mt < 2; mt++) {
        int r0 = m0 + mbase + mt * 16 + grp;
        int r1 = r0 + 8;
        float rs0 = 1.f, rs1 = 1.f;
        if (mode == 2) { rs0 = g_RS[r0]; rs1 = g_RS[r1]; }
        #pragma unroll
        for (int nt = 0; nt < 4; nt++) {
            int nc = n0 + nbase + nt * 8 + tg * 2;
            if (nc >= N) continue;
            float a0 = acc[mt][nt][0], a1 = acc[mt][nt][1];
            float a2 = acc[mt][nt][2], a3 = acc[mt][nt][3];
            if (mode == 3) {
                const float* t0 = g_T1 + (size_t)r0 * N + nc;
                const float* t1 = g_T1 + (size_t)r1 * N + nc;
                float2 g0 = *(const float2*)t0, g1 = *(const float2*)t1;
                float v00 = (g0.x / (1.f + __expf(-g0.x))) * a0;
                float v01 = (g0.y / (1.f + __expf(-g0.y))) * a1;
                float v10 = (g1.x / (1.f + __expf(-g1.x))) * a2;
                float v11 = (g1.y / (1.f + __expf(-g1.y))) * a3;
                __nv_bfloat16* h0 = g_Ghi + (size_t)r0 * N + nc;
                __nv_bfloat16* l0 = g_Glo + (size_t)r0 * N + nc;
                __nv_bfloat16* h1 = g_Ghi + (size_t)r1 * N + nc;
                __nv_bfloat16* l1 = g_Glo + (size_t)r1 * N + nc;
                split_store(h0, l0, v00);     split_store(h0 + 1, l0 + 1, v01);
                split_store(h1, l1, v10);     split_store(h1 + 1, l1 + 1, v11);
            } else {
                float* p0 = C + (size_t)r0 * N + nc;
                float* p1 = C + (size_t)r1 * N + nc;
                if (mode == 0) {
                    *(float2*)p0 = make_float2(a0, a1);
                    *(float2*)p1 = make_float2(a2, a3);
                } else {
                    float2 o0 = *(const float2*)p0, o1 = *(const float2*)p1;
                    *(float2*)p0 = make_float2(o0.x + rs0 * a0, o0.y + rs0 * a1);
                    *(float2*)p1 = make_float2(o1.x + rs1 * a2, o1.y + rs1 * a3);
                }
            }
        }
    }
}

// ---------------- RoPE in-place on q,k parts of g_QKV ------------------------
__global__ __launch_bounds__(160) void rope_kernel()
{
    int t = blockIdx.x;
    int s = t & (S_ - 1);
    int h = threadIdx.x >> 5;
    int i = threadIdx.x & 31;
    float freq = expf(-((float)(2 * i) / (float)HD_) * 9.210340371976184f);
    float ang = (float)s * freq;
    float sn, cs;
    sincosf(ang, &sn, &cs);
    float* qb = g_QKV + (size_t)t * QKVW_ + h * HD_;
    float q1 = qb[i], q2 = qb[i + 32];
    qb[i]      = q1 * cs - q2 * sn;
    qb[i + 32] = q2 * cs + q1 * sn;
    float* kb = qb + D_;
    float k1 = kb[i], k2 = kb[i + 32];
    kb[i]      = k1 * cs - k2 * sn;
    kb[i + 32] = k2 * cs + k1 * sn;
}

// ------ causal flash attention; epilogue writes bf16 hi/lo (stride D_) -------
__global__ __launch_bounds__(128) void attn_kernel()
{
    int qb = blockIdx.x, h = blockIdx.y, b = blockIdx.z;
    int tid = threadIdx.x;
    int sq = qb * 128 + tid;
    const float4* qp = (const float4*)(g_QKV + (size_t)(b * S_ + sq) * QKVW_ + h * HD_);
    ull q2r[32], o2[32];
    #pragma unroll
    for (int i = 0; i < 16; i++) {
        float4 v = qp[i];
        q2r[2*i+0] = pk2(v.x * 0.125f, v.y * 0.125f);
        q2r[2*i+1] = pk2(v.z * 0.125f, v.w * 0.125f);
    }
    #pragma unroll
    for (int i = 0; i < 32; i++) o2[i] = 0ULL;
    float m = -1e30f, l = 0.f;
    __shared__ __align__(16) float Ks[64 * 64];
    __shared__ __align__(16) float Vs[64 * 64];
    int kend = qb * 128 + 128;
    for (int j0 = 0; j0 < kend; j0 += 64) {
        __syncthreads();
        #pragma unroll
        for (int it = 0; it < 8; it++) {
            int idx = it * 128 + tid;
            int r = idx >> 4, c4 = idx & 15;
            const float4* kv = (const float4*)(g_QKV + (size_t)(b * S_ + j0 + r) * QKVW_ + h * HD_);
            ((float4*)Ks)[idx] = kv[80 + c4];
            ((float4*)Vs)[idx] = kv[160 + c4];
        }
        __syncthreads();
        if (j0 > sq) continue;
        int jm = sq - j0;
        int jend = (jm >= 63) ? 64 : (jm + 1);
        for (int j = 0; j < jend; j++) {
            const ulonglong2* kr = (const ulonglong2*)(Ks + j * 64);
            ull sa = 0ULL, sb2 = 0ULL, sc = 0ULL, sd = 0ULL;
            #pragma unroll
            for (int i = 0; i < 8; i++) {
                ulonglong2 k0 = kr[2*i], k1 = kr[2*i+1];
                sa  = fma2(q2r[4*i+0], k0.x, sa);
                sb2 = fma2(q2r[4*i+1], k0.y, sb2);
                sc  = fma2(q2r[4*i+2], k1.x, sc);
                sd  = fma2(q2r[4*i+3], k1.y, sd);
            }
            float2 sf = upk(add2(add2(sa, sb2), add2(sc, sd)));
            float s = sf.x + sf.y;
            if (s > m) {
                float c = __expf(m - s);
                m = s; l *= c;
                ull c2 = pk2(c, c);
                #pragma unroll
                for (int i = 0; i < 32; i++) o2[i] = mul2(o2[i], c2);
            }
            float p = __expf(s - m);
            l += p;
            ull p2 = pk2(p, p);
            const ulonglong2* vr = (const ulonglong2*)(Vs + j * 64);
            #pragma unroll
            for (int i = 0; i < 16; i++) {
                ulonglong2 vv = vr[i];
                o2[2*i+0] = fma2(p2, vv.x, o2[2*i+0]);
                o2[2*i+1] = fma2(p2, vv.y, o2[2*i+1]);
            }
        }
    }
    float invl = 1.f / l;
    __nv_bfloat16* hi = g_Ahi + (size_t)(b * S_ + sq) * D_ + h * HD_;
    __nv_bfloat16* lo = g_Alo + (size_t)(b * S_ + sq) * D_ + h * HD_;
    #pragma unroll
    for (int i = 0; i < 16; i++) {
        float2 a = upk(o2[2*i]), c = upk(o2[2*i+1]);
        split_store(hi + 4*i + 0, lo + 4*i + 0, a.x * invl);
        split_store(hi + 4*i + 1, lo + 4*i + 1, a.y * invl);
        split_store(hi + 4*i + 2, lo + 4*i + 2, c.x * invl);
        split_store(hi + 4*i + 3, lo + 4*i + 3, c.y * invl);
    }
}

// ---------------- router: sigmoid(X . router_w) one warp per token -----------
__global__ __launch_bounds__(128) void router_kernel(const float* __restrict__ rw)
{
    int t = blockIdx.x * 4 + (threadIdx.x >> 5);
    int lane = threadIdx.x & 31;
    const float* x = g_X + (size_t)t * D_;
    float s = 0.f;
    for (int d = lane; d < D_; d += 32) s = fmaf(x[d], rw[d], s);
    #pragma unroll
    for (int o = 16; o > 0; o >>= 1) s += __shfl_xor_sync(0xffffffffu, s, o);
    if (lane == 0) g_P[t] = 1.f / (1.f + expf(-s));
}

// ---------------- exact stable top-k selection -> g_RS = mask * prob ---------
__global__ __launch_bounds__(256) void select_kernel()
{
    __shared__ float p[S_];
    int b = blockIdx.x;
    for (int t = threadIdx.x; t < S_; t += 256) p[t] = g_P[b * S_ + t];
    __syncthreads();
    int t = blockIdx.y * 256 + threadIdx.x;
    float pt = p[t];
    int rank = 0;
    for (int j = 0; j < S_; j++) {
        float pj = p[j];
        rank += (pj > pt) ? 1 : ((pj == pt && j < t) ? 1 : 0);
    }
    g_RS[b * S_ + t] = (rank < KSEL_) ? pt : 0.f;
}

// ---------------- driver ------------------------------------------------------
extern "C" void kernel_launch(void* const* d_in, const int* in_sizes, int n_in,
                              void* d_out, int out_size)
{
    const int*   ids          = (const int*)d_in[0];
    const int*   iter         = (const int*)d_in[1];
    const float* emb          = (const float*)d_in[2];
    const float* iemb         = (const float*)d_in[3];
    const float* attn_norm_w  = (const float*)d_in[4];
    const float* Wqkv         = (const float*)d_in[5];
    const float* wo_w         = (const float*)d_in[6];
    const float* router_w     = (const float*)d_in[7];
    const float* mlp_norm_w   = (const float*)d_in[8];
    const float* gate_w       = (const float*)d_in[9];
    const float* up_w         = (const float*)d_in[10];
    const float* down_w       = (const float*)d_in[11];
    const float* final_norm_w = (const float*)d_in[12];
    float* out = (float*)d_out;

    cudaFuncSetAttribute(mma_gemm_kernel,
                         cudaFuncAttributeMaxDynamicSharedMemorySize, SMEM_MM);

    embed_kernel<<<TOK_, 128>>>(ids, iter, emb, iemb);                 // 0
    for (int l = 0; l < NL_; l++) {
        rmsnorm_kernel<<<TOK_, 128>>>(attn_norm_w + l * D_, nullptr);  // 1
        conv_w_kernel<<<QKVW_, 128>>>(Wqkv + (size_t)l * QKVW_ * D_, D_); // 2
        mma_gemm_kernel<<<dim3(15, 128), 256, SMEM_MM>>>(QKVW_, D_, 10, 0, 0, 0); // 3 <- profiled
        rope_kernel<<<TOK_, 160>>>();
        attn_kernel<<<dim3(S_ / 128, NH_, B_), 128>>>();
        conv_w_kernel<<<D_, 128>>>(wo_w + (size_t)l * D_ * D_, D_);
        mma_gemm_kernel<<<dim3(5, 128), 256, SMEM_MM>>>(D_, D_, 10, 1, 1, 0);
        router_kernel<<<TOK_ / 4, 128>>>(router_w + l * D_);
        select_kernel<<<dim3(B_, 8), 256>>>();
        rmsnorm_kernel<<<TOK_, 128>>>(mlp_norm_w + l * D_, nullptr);
        conv_w_kernel<<<FF_, 128>>>(gate_w + (size_t)l * FF_ * D_, D_);
        mma_gemm_kernel<<<dim3(14, 128), 256, SMEM_MM>>>(FF_, D_, 10, 0, 2, 0);  // T1
        conv_w_kernel<<<FF_, 128>>>(up_w + (size_t)l * FF_ * D_, D_);
        mma_gemm_kernel<<<dim3(14, 128), 256, SMEM_MM>>>(FF_, D_, 10, 3, 2, 0);  // G hi/lo
        conv_w_kernel<<<D_, 128>>>(down_w + (size_t)l * D_ * FF_, FF_);
        mma_gemm_kernel<<<dim3(5, 128), 256, SMEM_MM>>>(D_, FF_, 27, 2, 1, 1);   // X += rs*down
    }
    rmsnorm_kernel<<<TOK_, 128>>>(final_norm_w, out);
}